// round 15
// baseline (speedup 1.0000x reference)
#include <cuda_runtime.h>
#include <cuda_fp16.h>
#include <cstdint>

// Residual quantizer: tf32 mma.sync (legacy tensor path, HMMA - compiles for
// plain sm_103 target, unlike tcgen05 which is 'a'-feature gated) computes
// approximate distances for all 256 codes; candidates within a provable
// error margin of the approx min are re-checked with the EXACT validated
// fp32 chain (sequential fmaf, reference association, ascending-k strict-<).
// Produced indices are bitwise identical to exact evaluation of all codes
// (rel_err 7.351969e-4, validated rounds 2-13).
// 1 CTA = 128 points = 128 threads (4 warps x 32 rows). Per level:
//   stage exact residual->tf32 A smem, codebook->tf32 B smem (+exact c2),
//   m16n8k8 sweep (M=32/warp, N=256, K=64), dist->fp16 smem, per-row amin,
//   per-thread candidate scan + exact re-check, exact residual update.

#define KCODES 256
#define DIM 64
#define LEVELS 4
#define TPB 128

// smem (bytes)
#define SM_RS    0                     // exact residual 128 x stride65 f32
#define SM_AS    33280                 // tf32 A 128 x stride68 u32
#define SM_BS    68096                 // tf32 B 256 x stride68 u32
#define SM_DS    137728                // fp16 dist 128 rows x stride129 u32
#define SM_C2    203776                // 256 f32
#define SM_R2S   204800                // 128 f32
#define SM_AMIN  205312                // 128 f32
#define SM_WMAX  205824                // 4 f32
#define SMEM_TOTAL 205840

#define RS_STRIDE 65
#define AB_STRIDE 68
#define DS_STRIDE 129

#define CVT_TF32(u, f) asm("cvt.rna.tf32.f32 %0, %1;" : "=r"(u) : "f"(f))

#define MMA_TF32(d, a, b)                                                   \
    asm volatile(                                                           \
        "mma.sync.aligned.m16n8k8.row.col.f32.tf32.tf32.f32 "               \
        "{%0,%1,%2,%3}, {%4,%5,%6,%7}, {%8,%9}, {%0,%1,%2,%3};"             \
        : "+f"((d)[0]), "+f"((d)[1]), "+f"((d)[2]), "+f"((d)[3])            \
        : "r"((a)[0]), "r"((a)[1]), "r"((a)[2]), "r"((a)[3]),               \
          "r"((b)[0]), "r"((b)[1]))

__global__ void __launch_bounds__(TPB)
rq_mma_kernel(const float* __restrict__ z, const float* __restrict__ cb,
              float* __restrict__ out, int B) {
    extern __shared__ __align__(16) char smem[];
    float*    Rs   = reinterpret_cast<float*>(smem + SM_RS);
    uint32_t* As32 = reinterpret_cast<uint32_t*>(smem + SM_AS);
    uint32_t* Bs32 = reinterpret_cast<uint32_t*>(smem + SM_BS);
    uint32_t* Ds32 = reinterpret_cast<uint32_t*>(smem + SM_DS);
    float*    c2   = reinterpret_cast<float*>(smem + SM_C2);
    float*    r2s  = reinterpret_cast<float*>(smem + SM_R2S);
    float*    aminS= reinterpret_cast<float*>(smem + SM_AMIN);
    float*    wmax = reinterpret_cast<float*>(smem + SM_WMAX);

    const int tid = threadIdx.x;
    const int wid = tid >> 5;
    const int lane = tid & 31;
    const int g = lane >> 2;       // group 0..7
    const int t4 = lane & 3;       // 0..3
    const long p_raw = (long)blockIdx.x * TPB + tid;
    const long p = p_raw < B ? p_raw : (B - 1);

    // ---- init exact residual Rs[tid][j] = z[p][j] ----
    {
        const float4* zp = reinterpret_cast<const float4*>(z + p * DIM);
        float* rrow = Rs + tid * RS_STRIDE;
#pragma unroll
        for (int i = 0; i < 16; i++) {
            float4 v = zp[i];
            rrow[4 * i + 0] = v.x; rrow[4 * i + 1] = v.y;
            rrow[4 * i + 2] = v.z; rrow[4 * i + 3] = v.w;
        }
    }

    int ids[LEVELS];

#pragma unroll 1
    for (int lvl = 0; lvl < LEVELS; lvl++) {
        __syncthreads();   // prior level fully consumed As/Bs/Ds

        // ---- stage B (2 codes/thread): tf32 smem + exact c2 ----
        float lmax = 0.f;
#pragma unroll 1
        for (int s = 0; s < 2; s++) {
            const int k = tid + s * 128;
            const float4* src = reinterpret_cast<const float4*>(
                cb + ((size_t)lvl * KCODES + k) * DIM);
            float acc = 0.f;
            uint32_t* brow = Bs32 + k * AB_STRIDE;
#pragma unroll
            for (int i = 0; i < 16; i++) {
                float4 v = __ldg(src + i);
                acc = __fadd_rn(acc, __fmul_rn(v.x, v.x));
                acc = __fadd_rn(acc, __fmul_rn(v.y, v.y));
                acc = __fadd_rn(acc, __fmul_rn(v.z, v.z));
                acc = __fadd_rn(acc, __fmul_rn(v.w, v.w));
                uint4 u;
                CVT_TF32(u.x, v.x); CVT_TF32(u.y, v.y);
                CVT_TF32(u.z, v.z); CVT_TF32(u.w, v.w);
                *reinterpret_cast<uint4*>(brow + 4 * i) = u;
            }
            c2[k] = acc;
            lmax = fmaxf(lmax, acc);
        }
#pragma unroll
        for (int o = 16; o >= 1; o >>= 1)
            lmax = fmaxf(lmax, __shfl_xor_sync(0xffffffffu, lmax, o));
        if (lane == 0) wmax[wid] = lmax;

        // ---- stage A row + exact r2 ----
        {
            const float* rrow = Rs + tid * RS_STRIDE;
            uint32_t* arow = As32 + tid * AB_STRIDE;
            float r2 = 0.f;
#pragma unroll
            for (int i = 0; i < 16; i++) {
                float v0 = rrow[4 * i + 0], v1 = rrow[4 * i + 1];
                float v2 = rrow[4 * i + 2], v3 = rrow[4 * i + 3];
                r2 = __fadd_rn(r2, __fmul_rn(v0, v0));
                r2 = __fadd_rn(r2, __fmul_rn(v1, v1));
                r2 = __fadd_rn(r2, __fmul_rn(v2, v2));
                r2 = __fadd_rn(r2, __fmul_rn(v3, v3));
                uint4 u;
                CVT_TF32(u.x, v0); CVT_TF32(u.y, v1);
                CVT_TF32(u.z, v2); CVT_TF32(u.w, v3);
                *reinterpret_cast<uint4*>(arow + 4 * i) = u;
            }
            r2s[tid] = r2;
        }
        __syncthreads();
        const float c2max = fmaxf(fmaxf(wmax[0], wmax[1]),
                                  fmaxf(wmax[2], wmax[3]));

        // ---- MMA sweep: warp rows [32w,32w+32), N=256, K=64 ----
        {
            const int rowbase = 32 * wid;
            uint32_t afr[2][8][4];
#pragma unroll
            for (int mt = 0; mt < 2; mt++) {
                const uint32_t* ap0 =
                    As32 + (rowbase + 16 * mt + g) * AB_STRIDE + t4;
#pragma unroll
                for (int ks = 0; ks < 8; ks++) {
                    afr[mt][ks][0] = ap0[ks * 8];
                    afr[mt][ks][1] = ap0[8 * AB_STRIDE + ks * 8];
                    afr[mt][ks][2] = ap0[ks * 8 + 4];
                    afr[mt][ks][3] = ap0[8 * AB_STRIDE + ks * 8 + 4];
                }
            }
            float r2r[2][2];
#pragma unroll
            for (int mt = 0; mt < 2; mt++) {
                r2r[mt][0] = r2s[rowbase + 16 * mt + g];
                r2r[mt][1] = r2s[rowbase + 16 * mt + g + 8];
            }
            float am[2][2] = {{__int_as_float(0x7F800000),
                               __int_as_float(0x7F800000)},
                              {__int_as_float(0x7F800000),
                               __int_as_float(0x7F800000)}};

#pragma unroll 1
            for (int np = 0; np < 16; np++) {   // pairs of n8 tiles
                const int n0 = np * 16;
                uint32_t bf[2][8][2];
#pragma unroll
                for (int u = 0; u < 2; u++) {
                    const uint32_t* bp =
                        Bs32 + (n0 + 8 * u + g) * AB_STRIDE + t4;
#pragma unroll
                    for (int ks = 0; ks < 8; ks++) {
                        bf[u][ks][0] = bp[ks * 8];
                        bf[u][ks][1] = bp[ks * 8 + 4];
                    }
                }
                float d[2][2][4];
#pragma unroll
                for (int mt = 0; mt < 2; mt++)
#pragma unroll
                    for (int u = 0; u < 2; u++)
#pragma unroll
                        for (int q = 0; q < 4; q++) d[mt][u][q] = 0.f;
#pragma unroll
                for (int ks = 0; ks < 8; ks++) {
                    MMA_TF32(d[0][0], afr[0][ks], bf[0][ks]);
                    MMA_TF32(d[1][0], afr[1][ks], bf[0][ks]);
                    MMA_TF32(d[0][1], afr[0][ks], bf[1][ks]);
                    MMA_TF32(d[1][1], afr[1][ks], bf[1][ks]);
                }
                // dist -> fp16 store + running row-min
#pragma unroll
                for (int mt = 0; mt < 2; mt++) {
#pragma unroll
                    for (int u = 0; u < 2; u++) {
                        const int col = n0 + 8 * u + 2 * t4;
                        const float cc0 = c2[col], cc1 = c2[col + 1];
                        const int r0 = rowbase + 16 * mt + g;
                        float q00 = __fadd_rn(
                            __fsub_rn(r2r[mt][0],
                                      __fmul_rn(2.0f, d[mt][u][0])), cc0);
                        float q01 = __fadd_rn(
                            __fsub_rn(r2r[mt][0],
                                      __fmul_rn(2.0f, d[mt][u][1])), cc1);
                        float q10 = __fadd_rn(
                            __fsub_rn(r2r[mt][1],
                                      __fmul_rn(2.0f, d[mt][u][2])), cc0);
                        float q11 = __fadd_rn(
                            __fsub_rn(r2r[mt][1],
                                      __fmul_rn(2.0f, d[mt][u][3])), cc1);
                        __half h00 = __float2half_rn(q00);
                        __half h01 = __float2half_rn(q01);
                        __half h10 = __float2half_rn(q10);
                        __half h11 = __float2half_rn(q11);
                        uint32_t w0 =
                            ((uint32_t)__half_as_ushort(h01) << 16) |
                            (uint32_t)__half_as_ushort(h00);
                        uint32_t w1 =
                            ((uint32_t)__half_as_ushort(h11) << 16) |
                            (uint32_t)__half_as_ushort(h10);
                        Ds32[r0 * DS_STRIDE + col / 2] = w0;
                        Ds32[(r0 + 8) * DS_STRIDE + col / 2] = w1;
                        am[mt][0] = fminf(am[mt][0],
                            fminf(__half2float(h00), __half2float(h01)));
                        am[mt][1] = fminf(am[mt][1],
                            fminf(__half2float(h10), __half2float(h11)));
                    }
                }
            }
            // reduce row-min across the 4 lanes of each group
#pragma unroll
            for (int mt = 0; mt < 2; mt++) {
#pragma unroll
                for (int o = 1; o <= 2; o <<= 1) {
                    am[mt][0] = fminf(am[mt][0],
                        __shfl_xor_sync(0xffffffffu, am[mt][0], o));
                    am[mt][1] = fminf(am[mt][1],
                        __shfl_xor_sync(0xffffffffu, am[mt][1], o));
                }
                if (t4 == 0) {
                    aminS[rowbase + 16 * mt + g] = am[mt][0];
                    aminS[rowbase + 16 * mt + g + 8] = am[mt][1];
                }
            }
        }
        __syncthreads();

        // ---- candidate scan + exact re-check (ascending k, strict <) ----
        {
            const float r2 = r2s[tid];
            // margin >= 1.5x rigorous bound: tf32 dot err <= 1e-3*(r2+c2),
            // fp16 storage err (min+cand) <= 2e-3*(r2+c2)
            const float thr = aminS[tid] +
                              (4.5e-3f * (r2 + c2max) + 1e-4f);
            const uint32_t* drow = Ds32 + tid * DS_STRIDE;
            const float* rrow = Rs + tid * RS_STRIDE;
            float bestE = __int_as_float(0x7F800000);
            int bi = 0;
#pragma unroll 1
            for (int w = 0; w < 128; w++) {
                const uint32_t hw = drow[w];
                const float f0 =
                    __half2float(__ushort_as_half((unsigned short)(hw & 0xffffu)));
                const float f1 =
                    __half2float(__ushort_as_half((unsigned short)(hw >> 16)));
#pragma unroll
                for (int c = 0; c < 2; c++) {
                    const float fa = (c == 0) ? f0 : f1;
                    if (fa <= thr) {
                        const int k = 2 * w + c;
                        const float4* crow = reinterpret_cast<const float4*>(
                            cb + ((size_t)lvl * KCODES + k) * DIM);
                        float dot = 0.f;
#pragma unroll
                        for (int i2 = 0; i2 < 16; i2++) {
                            float4 cv = __ldg(crow + i2);
                            dot = fmaf(rrow[4 * i2 + 0], cv.x, dot);
                            dot = fmaf(rrow[4 * i2 + 1], cv.y, dot);
                            dot = fmaf(rrow[4 * i2 + 2], cv.z, dot);
                            dot = fmaf(rrow[4 * i2 + 3], cv.w, dot);
                        }
                        float de = __fadd_rn(
                            __fsub_rn(r2, __fmul_rn(2.0f, dot)), c2[k]);
                        if (de < bestE) { bestE = de; bi = k; }
                    }
                }
            }
            ids[lvl] = bi;

            // ---- exact residual update (gmem gather; validated) ----
            const float4* cw = reinterpret_cast<const float4*>(
                cb + ((size_t)lvl * KCODES + bi) * DIM);
            float* rw = Rs + tid * RS_STRIDE;
#pragma unroll
            for (int i = 0; i < 16; i++) {
                float4 cv = __ldg(cw + i);
                rw[4 * i + 0] = __fsub_rn(rw[4 * i + 0], cv.x);
                rw[4 * i + 1] = __fsub_rn(rw[4 * i + 1], cv.y);
                rw[4 * i + 2] = __fsub_rn(rw[4 * i + 2], cv.z);
                rw[4 * i + 3] = __fsub_rn(rw[4 * i + 3], cv.w);
            }
        }
    }

    if (p_raw >= B) return;

    // ---- epilogue (chunk-wise; validated bitwise vs reference) ----
    {
        const float4* cp0 = reinterpret_cast<const float4*>(
            cb + ((size_t)0 * KCODES + ids[0]) * DIM);
        const float4* cp1 = reinterpret_cast<const float4*>(
            cb + ((size_t)1 * KCODES + ids[1]) * DIM);
        const float4* cp2 = reinterpret_cast<const float4*>(
            cb + ((size_t)2 * KCODES + ids[2]) * DIM);
        const float4* cp3 = reinterpret_cast<const float4*>(
            cb + ((size_t)3 * KCODES + ids[3]) * DIM);
        const float4* zp = reinterpret_cast<const float4*>(z + p * DIM);
        float4* qst = reinterpret_cast<float4*>(out + (size_t)p * DIM);
        float4* qq  = reinterpret_cast<float4*>(out + (size_t)B * (DIM + 4) +
                                                (size_t)p * DIM);
#pragma unroll
        for (int i = 0; i < 16; i++) {
            float4 v0 = __ldg(cp0 + i), v1 = __ldg(cp1 + i);
            float4 v2 = __ldg(cp2 + i), v3 = __ldg(cp3 + i);
            float4 qv;
            qv.x = __fadd_rn(__fadd_rn(__fadd_rn(v0.x, v1.x), v2.x), v3.x);
            qv.y = __fadd_rn(__fadd_rn(__fadd_rn(v0.y, v1.y), v2.y), v3.y);
            qv.z = __fadd_rn(__fadd_rn(__fadd_rn(v0.z, v1.z), v2.z), v3.z);
            qv.w = __fadd_rn(__fadd_rn(__fadd_rn(v0.w, v1.w), v2.w), v3.w);
            float4 zv = zp[i];
            float4 sv;
            sv.x = __fadd_rn(zv.x, __fsub_rn(qv.x, zv.x));
            sv.y = __fadd_rn(zv.y, __fsub_rn(qv.y, zv.y));
            sv.z = __fadd_rn(zv.z, __fsub_rn(qv.z, zv.z));
            sv.w = __fadd_rn(zv.w, __fsub_rn(qv.w, zv.w));
            qst[i] = sv;
            qq[i] = qv;
        }
        float4 iv;
        iv.x = (float)ids[0]; iv.y = (float)ids[1];
        iv.z = (float)ids[2]; iv.w = (float)ids[3];
        reinterpret_cast<float4*>(out + (size_t)B * DIM)[p] = iv;
    }
}

extern "C" void kernel_launch(void* const* d_in, const int* in_sizes, int n_in,
                              void* d_out, int out_size) {
    const float* z = (const float*)d_in[0];
    const float* cb = (const float*)d_in[1];
    float* out = (float*)d_out;
    int B = in_sizes[0] / DIM;

    cudaFuncSetAttribute(rq_mma_kernel,
                         cudaFuncAttributeMaxDynamicSharedMemorySize,
                         SMEM_TOTAL);
    int blocks = (B + TPB - 1) / TPB;
    rq_mma_kernel<<<blocks, TPB, SMEM_TOTAL>>>(z, cb, out, B);
}

// round 16
// speedup vs baseline: 1.0112x; 1.0112x over previous
#include <cuda_runtime.h>
#include <cuda_fp16.h>
#include <cstdint>

// Residual quantizer: tf32 mma.sync filter + exact re-check (scheme validated
// round 15: indices bitwise-identical to exact evaluation, rel_err
// 7.351969e-4). This round: performance rework of the passing kernel.
//  * B staged in FRAGMENT-MAJOR smem layout -> sweep loads 4x uint4 per
//    ntile (was 16 strided LDS.32): -75% B-load instructions.
//  * s-scale scores: s = dot - c2/2 (argmin dist == argmax s; r2 drops out
//    of the sweep epilogue); fp16x2 packing via cvt.rn.f16x2.f32, running
//    max via HMAX2.
//  * TPB=256 / 8 warps: per-warp M=16 (afr 32 regs, sweep-live ~100 < 128
//    cap, no spill); point-parallel phases use 2 same-warp threads/point
//    with shfl combine (tie -> lower k preserved).
//  * vectorized candidate scan: uint4 + HMAX2 fast reject, 16 iters.
// Exact paths (r2/c2 chains, re-check, update, epilogue, association,
// ascending-k strict-<) are byte-identical to validated rounds.

#define KCODES 256
#define DIM 64
#define LEVELS 4
#define TPB 256
#define PTS 128                    // points per CTA

#define RS_STRIDE 65               // Rs row stride (f32 words)
#define AB_STRIDE 68               // As row stride (u32 words)
#define DS_STRIDE 132              // Ds row stride (u32 words)

// smem byte offsets
#define SM_RS    0                              // 128*65*4  = 33280
#define SM_AS    33280                          // 128*68*4  = 34816
#define SM_BF    68096                          // 32*640*4  = 81920
#define SM_DS    150016                         // 128*132*4 = 67584
#define SM_C2    217600                         // 256*4
#define SM_C2H   218624                         // 256*4
#define SM_R2S   219648                         // 128*4
#define SM_SMAX  220160                         // 128*4
#define SM_WMAX  220672                         // 8*4
#define SMEM_TOTAL 220704

#define CVT_TF32(u, f) asm("cvt.rna.tf32.f32 %0, %1;" : "=r"(u) : "f"(f))
// pack two f32 -> f16x2: low half = lo, high half = hi
#define CVT_F16X2(out, hi, lo) \
    asm("cvt.rn.f16x2.f32 %0, %1, %2;" : "=r"(out) : "f"(hi), "f"(lo))

#define MMA_TF32(d, a, b0, b1)                                              \
    asm volatile(                                                           \
        "mma.sync.aligned.m16n8k8.row.col.f32.tf32.tf32.f32 "               \
        "{%0,%1,%2,%3}, {%4,%5,%6,%7}, {%8,%9}, {%0,%1,%2,%3};"             \
        : "+f"((d)[0]), "+f"((d)[1]), "+f"((d)[2]), "+f"((d)[3])            \
        : "r"((a)[0]), "r"((a)[1]), "r"((a)[2]), "r"((a)[3]),               \
          "r"(b0), "r"(b1))

static __device__ __forceinline__ __half2 u2h2(uint32_t u) {
    return *reinterpret_cast<__half2*>(&u);
}

__global__ void __launch_bounds__(TPB)
rq_mma_kernel(const float* __restrict__ z, const float* __restrict__ cb,
              float* __restrict__ out, int B) {
    extern __shared__ __align__(16) char smem[];
    float*    Rs   = reinterpret_cast<float*>(smem + SM_RS);
    uint32_t* As32 = reinterpret_cast<uint32_t*>(smem + SM_AS);
    uint32_t* BF32 = reinterpret_cast<uint32_t*>(smem + SM_BF);
    uint32_t* Ds32 = reinterpret_cast<uint32_t*>(smem + SM_DS);
    float*    c2   = reinterpret_cast<float*>(smem + SM_C2);
    float*    c2h  = reinterpret_cast<float*>(smem + SM_C2H);
    float*    r2s  = reinterpret_cast<float*>(smem + SM_R2S);
    float*    smaxS= reinterpret_cast<float*>(smem + SM_SMAX);
    float*    wmax = reinterpret_cast<float*>(smem + SM_WMAX);

    const int tid = threadIdx.x;
    const int wid = tid >> 5;
    const int lane = tid & 31;
    const int g = lane >> 2;
    const int t4 = lane & 3;
    const int q = tid >> 1;        // my point (2 threads per point)
    const int h = tid & 1;         // half index within the pair
    const long p_raw = (long)blockIdx.x * PTS + q;
    const long p = p_raw < B ? p_raw : (B - 1);

    // ---- init exact residual (pair-split chunks) ----
    {
        const float4* zp = reinterpret_cast<const float4*>(z + p * DIM);
        float* rrow = Rs + q * RS_STRIDE;
#pragma unroll
        for (int i = h * 8; i < h * 8 + 8; i++) {
            float4 v = zp[i];
            rrow[4 * i + 0] = v.x; rrow[4 * i + 1] = v.y;
            rrow[4 * i + 2] = v.z; rrow[4 * i + 3] = v.w;
        }
    }

    int ids[LEVELS];

#pragma unroll 1
    for (int lvl = 0; lvl < LEVELS; lvl++) {
        __syncthreads();   // prior level fully consumed As/BF/Ds

        // ---- stage B code n=tid: frag-major tf32 + exact c2 chain ----
        {
            const int n = tid;
            const float4* src = reinterpret_cast<const float4*>(
                cb + ((size_t)lvl * KCODES + n) * DIM);
            const int nt = n >> 3, gg = n & 7;
            uint32_t* dst = BF32 + nt * 640 + gg * 80;  // + t4w*20 later
            float acc = 0.f;
#pragma unroll
            for (int i = 0; i < 16; i++) {
                float4 v = __ldg(src + i);
                acc = __fadd_rn(acc, __fmul_rn(v.x, v.x));
                acc = __fadd_rn(acc, __fmul_rn(v.y, v.y));
                acc = __fadd_rn(acc, __fmul_rn(v.z, v.z));
                acc = __fadd_rn(acc, __fmul_rn(v.w, v.w));
                uint32_t u0, u1, u2, u3;
                CVT_TF32(u0, v.x); CVT_TF32(u1, v.y);
                CVT_TF32(u2, v.z); CVT_TF32(u3, v.w);
                // k = 4i+c: ks = k>>3, km8 = k&7, slot = km8>>2, t4w = km8&3
                const int k0 = 4 * i;
#pragma unroll
                for (int c = 0; c < 4; c++) {
                    const int k = k0 + c;
                    const uint32_t uv = (c == 0) ? u0 : (c == 1) ? u1
                                       : (c == 2) ? u2 : u3;
                    const int km8 = k & 7;
                    dst[(km8 & 3) * 20 + (k >> 3) * 2 + (km8 >> 2)] = uv;
                }
            }
            c2[n] = acc;
            c2h[n] = 0.5f * acc;      // exact scaling (power of 2)
            float lmax = acc;
#pragma unroll
            for (int o = 16; o >= 1; o >>= 1)
                lmax = fmaxf(lmax, __shfl_xor_sync(0xffffffffu, lmax, o));
            if (lane == 0) wmax[wid] = lmax;
        }

        // ---- stage A row q (pair-split) + exact r2 (h==0 chain) ----
        {
            const float* rrow = Rs + q * RS_STRIDE;
            uint32_t* arow = As32 + q * AB_STRIDE;
#pragma unroll
            for (int i = h * 8; i < h * 8 + 8; i++) {
                uint4 u;
                CVT_TF32(u.x, rrow[4 * i + 0]);
                CVT_TF32(u.y, rrow[4 * i + 1]);
                CVT_TF32(u.z, rrow[4 * i + 2]);
                CVT_TF32(u.w, rrow[4 * i + 3]);
                *reinterpret_cast<uint4*>(arow + 4 * i) = u;
            }
            if (h == 0) {
                float r2 = 0.f;
#pragma unroll
                for (int j = 0; j < DIM; j++)
                    r2 = __fadd_rn(r2, __fmul_rn(rrow[j], rrow[j]));
                r2s[q] = r2;
            }
        }
        __syncthreads();

        // ---- MMA sweep: warp rows [16w,16w+16), N=256, K=64 ----
        {
            const int rowbase = 16 * wid;
            uint32_t afr[8][4];
            const uint32_t* ap0 = As32 + (rowbase + g) * AB_STRIDE + t4;
#pragma unroll
            for (int ks = 0; ks < 8; ks++) {
                afr[ks][0] = ap0[ks * 8];
                afr[ks][1] = ap0[8 * AB_STRIDE + ks * 8];
                afr[ks][2] = ap0[ks * 8 + 4];
                afr[ks][3] = ap0[8 * AB_STRIDE + ks * 8 + 4];
            }
            __half2 amx0 = u2h2(0xFC00FC00u);   // -inf,-inf
            __half2 amx1 = u2h2(0xFC00FC00u);

#pragma unroll 1
            for (int np = 0; np < 16; np++) {
                const int nt0 = 2 * np;
                const uint4* bp0 = reinterpret_cast<const uint4*>(
                    BF32 + nt0 * 640 + lane * 20);
                const uint4* bp1 = reinterpret_cast<const uint4*>(
                    BF32 + (nt0 + 1) * 640 + lane * 20);
                uint4 b0[4], b1[4];
#pragma unroll
                for (int j = 0; j < 4; j++) { b0[j] = bp0[j]; b1[j] = bp1[j]; }
                float d0[4] = {0.f, 0.f, 0.f, 0.f};
                float d1[4] = {0.f, 0.f, 0.f, 0.f};
#pragma unroll
                for (int j = 0; j < 4; j++) {
                    MMA_TF32(d0, afr[2 * j],     b0[j].x, b0[j].y);
                    MMA_TF32(d1, afr[2 * j],     b1[j].x, b1[j].y);
                    MMA_TF32(d0, afr[2 * j + 1], b0[j].z, b0[j].w);
                    MMA_TF32(d1, afr[2 * j + 1], b1[j].z, b1[j].w);
                }
                // epilogue: s = dot - c2h, fp16x2 pack, store + running max
#pragma unroll
                for (int u = 0; u < 2; u++) {
                    const float* dd = u ? d1 : d0;
                    const int col = (nt0 + u) * 8 + 2 * t4;
                    const float ch0 = c2h[col], ch1 = c2h[col + 1];
                    float s00 = __fsub_rn(dd[0], ch0);
                    float s01 = __fsub_rn(dd[1], ch1);
                    float s10 = __fsub_rn(dd[2], ch0);
                    float s11 = __fsub_rn(dd[3], ch1);
                    uint32_t w0, w1;
                    CVT_F16X2(w0, s01, s00);
                    CVT_F16X2(w1, s11, s10);
                    const int ci = (nt0 + u) * 4 + t4;
                    Ds32[(rowbase + g) * DS_STRIDE + ci] = w0;
                    Ds32[(rowbase + g + 8) * DS_STRIDE + ci] = w1;
                    amx0 = __hmax2(amx0, u2h2(w0));
                    amx1 = __hmax2(amx1, u2h2(w1));
                }
            }
            float sm0 = fmaxf(__low2float(amx0), __high2float(amx0));
            float sm1 = fmaxf(__low2float(amx1), __high2float(amx1));
#pragma unroll
            for (int o = 1; o <= 2; o <<= 1) {
                sm0 = fmaxf(sm0, __shfl_xor_sync(0xffffffffu, sm0, o));
                sm1 = fmaxf(sm1, __shfl_xor_sync(0xffffffffu, sm1, o));
            }
            if (t4 == 0) {
                smaxS[rowbase + g] = sm0;
                smaxS[rowbase + g + 8] = sm1;
            }
        }
        __syncthreads();

        // ---- candidate scan (vectorized) + exact re-check ----
        {
            const float r2 = r2s[q];
            float c2max = wmax[0];
#pragma unroll
            for (int i = 1; i < 8; i++) c2max = fmaxf(c2max, wmax[i]);
            // s-scale margin >= validated dist-scale margin / 2
            const float thr = smaxS[q] -
                              (2.5e-3f * (r2 + c2max) + 1e-4f);
            const uint4* dsrow = reinterpret_cast<const uint4*>(
                Ds32 + q * DS_STRIDE + h * 64);
            const float* rrow = Rs + q * RS_STRIDE;
            float bestE = __int_as_float(0x7F800000);
            int bi = 0;
#pragma unroll 1
            for (int i = 0; i < 16; i++) {
                const uint4 w = dsrow[i];
                __half2 m = __hmax2(__hmax2(u2h2(w.x), u2h2(w.y)),
                                    __hmax2(u2h2(w.z), u2h2(w.w)));
                const float mf = fmaxf(__low2float(m), __high2float(m));
                if (mf >= thr) {
                    const uint32_t ws[4] = {w.x, w.y, w.z, w.w};
#pragma unroll 1
                    for (int j = 0; j < 4; j++) {
                        const __half2 hv = u2h2(ws[j]);
                        const float s0 = __low2float(hv);
                        const float s1 = __high2float(hv);
#pragma unroll
                        for (int c = 0; c < 2; c++) {
                            const float sv = c ? s1 : s0;
                            if (sv >= thr) {
                                const int k = h * 128 + 8 * i + 2 * j + c;
                                const float4* crow =
                                    reinterpret_cast<const float4*>(
                                        cb + ((size_t)lvl * KCODES + k) * DIM);
                                float dot = 0.f;
#pragma unroll
                                for (int i2 = 0; i2 < 16; i2++) {
                                    float4 cv = __ldg(crow + i2);
                                    dot = fmaf(rrow[4 * i2 + 0], cv.x, dot);
                                    dot = fmaf(rrow[4 * i2 + 1], cv.y, dot);
                                    dot = fmaf(rrow[4 * i2 + 2], cv.z, dot);
                                    dot = fmaf(rrow[4 * i2 + 3], cv.w, dot);
                                }
                                float de = __fadd_rn(
                                    __fsub_rn(r2, __fmul_rn(2.0f, dot)),
                                    c2[k]);
                                if (de < bestE) { bestE = de; bi = k; }
                            }
                        }
                    }
                }
            }
            // combine across the pair (tie -> lower k)
            const float od = __shfl_xor_sync(0xffffffffu, bestE, 1);
            const int ok = __shfl_xor_sync(0xffffffffu, bi, 1);
            if (od < bestE || (od == bestE && ok < bi)) {
                bestE = od; bi = ok;
            }
            ids[lvl] = bi;
            __syncwarp();

            // ---- exact residual update (pair-split, elementwise) ----
            const float4* cw = reinterpret_cast<const float4*>(
                cb + ((size_t)lvl * KCODES + bi) * DIM);
            float* rw = Rs + q * RS_STRIDE;
#pragma unroll
            for (int i = h * 8; i < h * 8 + 8; i++) {
                float4 cv = __ldg(cw + i);
                rw[4 * i + 0] = __fsub_rn(rw[4 * i + 0], cv.x);
                rw[4 * i + 1] = __fsub_rn(rw[4 * i + 1], cv.y);
                rw[4 * i + 2] = __fsub_rn(rw[4 * i + 2], cv.z);
                rw[4 * i + 3] = __fsub_rn(rw[4 * i + 3], cv.w);
            }
        }
    }

    if (p_raw >= B) return;

    // ---- epilogue (chunk-wise, pair-split; validated vs reference) ----
    {
        const float4* cp0 = reinterpret_cast<const float4*>(
            cb + ((size_t)0 * KCODES + ids[0]) * DIM);
        const float4* cp1 = reinterpret_cast<const float4*>(
            cb + ((size_t)1 * KCODES + ids[1]) * DIM);
        const float4* cp2 = reinterpret_cast<const float4*>(
            cb + ((size_t)2 * KCODES + ids[2]) * DIM);
        const float4* cp3 = reinterpret_cast<const float4*>(
            cb + ((size_t)3 * KCODES + ids[3]) * DIM);
        const float4* zp = reinterpret_cast<const float4*>(z + p * DIM);
        float4* qst = reinterpret_cast<float4*>(out + (size_t)p * DIM);
        float4* qq  = reinterpret_cast<float4*>(out + (size_t)B * (DIM + 4) +
                                                (size_t)p * DIM);
#pragma unroll
        for (int i = h * 8; i < h * 8 + 8; i++) {
            float4 v0 = __ldg(cp0 + i), v1 = __ldg(cp1 + i);
            float4 v2 = __ldg(cp2 + i), v3 = __ldg(cp3 + i);
            // quantized = ((q0 + q1) + q2) + q3, sequential (matches ref)
            float4 qv;
            qv.x = __fadd_rn(__fadd_rn(__fadd_rn(v0.x, v1.x), v2.x), v3.x);
            qv.y = __fadd_rn(__fadd_rn(__fadd_rn(v0.y, v1.y), v2.y), v3.y);
            qv.z = __fadd_rn(__fadd_rn(__fadd_rn(v0.z, v1.z), v2.z), v3.z);
            qv.w = __fadd_rn(__fadd_rn(__fadd_rn(v0.w, v1.w), v2.w), v3.w);
            float4 zv = zp[i];
            float4 sv;
            sv.x = __fadd_rn(zv.x, __fsub_rn(qv.x, zv.x));
            sv.y = __fadd_rn(zv.y, __fsub_rn(qv.y, zv.y));
            sv.z = __fadd_rn(zv.z, __fsub_rn(qv.z, zv.z));
            sv.w = __fadd_rn(zv.w, __fsub_rn(qv.w, zv.w));
            qst[i] = sv;
            qq[i] = qv;
        }
        if (h == 0) {
            float4 iv;
            iv.x = (float)ids[0]; iv.y = (float)ids[1];
            iv.z = (float)ids[2]; iv.w = (float)ids[3];
            reinterpret_cast<float4*>(out + (size_t)B * DIM)[p] = iv;
        }
    }
}

extern "C" void kernel_launch(void* const* d_in, const int* in_sizes, int n_in,
                              void* d_out, int out_size) {
    const float* z = (const float*)d_in[0];
    const float* cb = (const float*)d_in[1];
    float* out = (float*)d_out;
    int B = in_sizes[0] / DIM;

    cudaFuncSetAttribute(rq_mma_kernel,
                         cudaFuncAttributeMaxDynamicSharedMemorySize,
                         SMEM_TOTAL);
    int blocks = (B + PTS - 1) / PTS;
    rq_mma_kernel<<<blocks, TPB, SMEM_TOTAL>>>(z, cb, out, B);
}

// round 17
// speedup vs baseline: 1.3829x; 1.3676x over previous
#include <cuda_runtime.h>
#include <cstdint>

// Residual quantizer: persistent-CTA bf16 mma.sync filter + exact re-check.
// Scheme (filter -> provable margin -> exact recheck) validated rounds 15/16
// with bit-identical indices (rel_err 7.351969e-4). This round removes the
// structural overhead that kept tensor at 8%:
//  * grid = #SMs, persistent CTAs; codebook staged ONCE per CTA for ALL 4
//    levels as bf16 frag-major (4 x 32 KB) + exact fp32 c2 -> staging cost
//    amortized over ~55 batches (was: per-CTA-per-level).
//  * sweep pass 1 computes row maxima in registers (no smem distance
//    matrix); threshold derived in-register (shfl); pass 2 recomputes the
//    bit-identical MMAs and pushes s >= thr candidates into per-row smem
//    lists (atomicAdd). Overflow (>CAP) falls back to full exact scan.
//  * a-fragments converted directly from the exact fp32 residual (no As).
// Margin (rigorous, 2-sided bf16 dot bound 2*2^-8*(r2+c2max) = 7.8e-3):
//   thr = smax - (1.0e-2*(r2+c2max) + 1e-3)  [1.28x bound + abs slack]
// Exact paths (c2/r2 chains, distance association, tie-break to lowest k,
// residual update, epilogue) are byte-identical to the validated kernels;
// list order does not affect the result (order-free tie-break).

#define KCODES 256
#define DIM 64
#define LEVELS 4
#define TPB 256
#define PTS 128
#define CAP 16
#define RS_STRIDE 66

// smem byte offsets
#define SM_BF    0                      // 4 lvl * 8192 u32 = 131072 B
#define SM_RS    131072                 // 128*66*4 = 33792
#define SM_C2    164864                 // 4*256*4 = 4096
#define SM_C2H   168960                 // 4096
#define SM_R2S   173056                 // 128*4 = 512
#define SM_CMAX  173568                 // 4*4 (pad 16)
#define SM_CNT   173584                 // 128*4 = 512
#define SM_LIST  174096                 // 128*16*4 = 8192
#define SMEM_TOTAL 182288

#define MARG_REL 1.0e-2f
#define MARG_ABS 1.0e-3f

// pack two fp32 -> bf16x2 (lo in bits[15:0])
#define PACK_BF16X2(out, hi, lo) \
    asm("cvt.rn.bf16x2.f32 %0, %1, %2;" : "=r"(out) : "f"(hi), "f"(lo))

#define MMA_BF16(d, a, bb0, bb1)                                            \
    asm volatile(                                                           \
        "mma.sync.aligned.m16n8k16.row.col.f32.bf16.bf16.f32 "              \
        "{%0,%1,%2,%3}, {%4,%5,%6,%7}, {%8,%9}, {%0,%1,%2,%3};"             \
        : "+f"((d)[0]), "+f"((d)[1]), "+f"((d)[2]), "+f"((d)[3])            \
        : "r"((a)[0]), "r"((a)[1]), "r"((a)[2]), "r"((a)[3]),               \
          "r"(bb0), "r"(bb1))

__global__ void __launch_bounds__(TPB)
rq_kernel(const float* __restrict__ z, const float* __restrict__ cb,
          float* __restrict__ out, int B, int nbatch) {
    extern __shared__ __align__(16) char smem[];
    uint32_t* BF   = reinterpret_cast<uint32_t*>(smem + SM_BF);
    float*    Rs   = reinterpret_cast<float*>(smem + SM_RS);
    float*    c2S  = reinterpret_cast<float*>(smem + SM_C2);
    float*    c2hS = reinterpret_cast<float*>(smem + SM_C2H);
    float*    r2sS = reinterpret_cast<float*>(smem + SM_R2S);
    float*    cmaxS= reinterpret_cast<float*>(smem + SM_CMAX);
    int*      cntS = reinterpret_cast<int*>(smem + SM_CNT);
    int*      listS= reinterpret_cast<int*>(smem + SM_LIST);

    const int tid = threadIdx.x;
    const int wid = tid >> 5;
    const int lane = tid & 31;
    const int g = lane >> 2;
    const int t4 = lane & 3;
    const int q = tid >> 1;           // my point (2 threads per point)
    const int h = tid & 1;
    const float NEGINF = __int_as_float(0xFF800000);

    // ==== one-time staging: all 4 levels, bf16 frag-major + exact c2 ====
#pragma unroll 1
    for (int lvl = 0; lvl < LEVELS; lvl++) {
        const int n = tid;            // TPB == KCODES
        const float4* src = reinterpret_cast<const float4*>(
            cb + ((size_t)lvl * KCODES + n) * DIM);
        float v[DIM];
#pragma unroll
        for (int i = 0; i < 16; i++) {
            float4 t = __ldg(src + i);
            v[4*i+0] = t.x; v[4*i+1] = t.y;
            v[4*i+2] = t.z; v[4*i+3] = t.w;
        }
        float acc = 0.f;
#pragma unroll
        for (int j = 0; j < DIM; j++)
            acc = __fadd_rn(acc, __fmul_rn(v[j], v[j]));   // exact chain
        c2S[lvl*KCODES + n] = acc;
        c2hS[lvl*KCODES + n] = 0.5f * acc;
        uint32_t w[32];
#pragma unroll
        for (int tw = 0; tw < 4; tw++)
#pragma unroll
            for (int ks = 0; ks < 8; ks++)
                PACK_BF16X2(w[tw*8+ks], v[8*ks+2*tw+1], v[8*ks+2*tw]);
        const int nt = n >> 3, gg = n & 7;
        uint32_t* dst = BF + lvl*8192 + nt*256 + gg*32;
#pragma unroll
        for (int i = 0; i < 8; i++)
            *reinterpret_cast<uint4*>(dst + 4*i) =
                *reinterpret_cast<const uint4*>(w + 4*i);
    }
    if (tid < PTS) cntS[tid] = 0;
    __syncthreads();
    if (wid < LEVELS) {               // per-level c2 max
        float m = NEGINF;
#pragma unroll
        for (int i = 0; i < 8; i++)
            m = fmaxf(m, c2S[wid*KCODES + lane + 32*i]);
#pragma unroll
        for (int o = 16; o >= 1; o >>= 1)
            m = fmaxf(m, __shfl_xor_sync(0xffffffffu, m, o));
        if (lane == 0) cmaxS[wid] = m;
    }
    // (visibility of cmaxS covered by the level-top __syncthreads below)

    // ==== batch loop ====
#pragma unroll 1
    for (int b = blockIdx.x; b < nbatch; b += gridDim.x) {
        const long p_raw = (long)b * PTS + q;
        const long p = p_raw < B ? p_raw : (B - 1);

        // z -> Rs (pair-split) + level-0 exact r2
        {
            const float4* zp = reinterpret_cast<const float4*>(z + p * DIM);
            float* rw = Rs + (size_t)q * RS_STRIDE;
#pragma unroll
            for (int i = h*8; i < h*8+8; i++) {
                float4 t = zp[i];
                rw[4*i+0] = t.x; rw[4*i+1] = t.y;
                rw[4*i+2] = t.z; rw[4*i+3] = t.w;
            }
            __syncwarp();
            if (h == 0) {
                float r2 = 0.f;
#pragma unroll
                for (int j = 0; j < DIM; j++)
                    r2 = __fadd_rn(r2, __fmul_rn(rw[j], rw[j]));
                r2sS[q] = r2;
            }
        }

        int ids_[LEVELS];

#pragma unroll 1
        for (int lvl = 0; lvl < LEVELS; lvl++) {
            __syncthreads();   // Rs/r2s of all pairs ready; lists zeroed

            // ---- a-fragments from exact residual (bf16) ----
            const int rowbase = wid * 16;
            const float* Ra = Rs + (size_t)(rowbase + g) * RS_STRIDE;
            const float* Rb = Rs + (size_t)(rowbase + g + 8) * RS_STRIDE;
            uint32_t afr[4][4];
#pragma unroll
            for (int kt = 0; kt < 4; kt++) {
                const int j0 = 16*kt + 2*t4;
                float2 a0 = *reinterpret_cast<const float2*>(Ra + j0);
                float2 a1 = *reinterpret_cast<const float2*>(Rb + j0);
                float2 a2 = *reinterpret_cast<const float2*>(Ra + j0 + 8);
                float2 a3 = *reinterpret_cast<const float2*>(Rb + j0 + 8);
                PACK_BF16X2(afr[kt][0], a0.y, a0.x);
                PACK_BF16X2(afr[kt][1], a1.y, a1.x);
                PACK_BF16X2(afr[kt][2], a2.y, a2.x);
                PACK_BF16X2(afr[kt][3], a3.y, a3.x);
            }
            const uint32_t* BL = BF + lvl*8192;
            const float* chL = c2hS + lvl*KCODES;

            // ---- pass 1: row maxima of s = dot - c2/2 ----
            float rm0 = NEGINF, rm1 = NEGINF;
#pragma unroll 2
            for (int nt = 0; nt < 32; nt++) {
                const uint4* bp = reinterpret_cast<const uint4*>(
                    BL + (nt*32 + lane)*8);
                uint4 bA = bp[0], bB = bp[1];
                float d[4] = {0.f, 0.f, 0.f, 0.f};
                MMA_BF16(d, afr[0], bA.x, bA.y);
                MMA_BF16(d, afr[1], bA.z, bA.w);
                MMA_BF16(d, afr[2], bB.x, bB.y);
                MMA_BF16(d, afr[3], bB.z, bB.w);
                const float2 ch = *reinterpret_cast<const float2*>(
                    chL + nt*8 + 2*t4);
                rm0 = fmaxf(rm0, fmaxf(__fsub_rn(d[0], ch.x),
                                       __fsub_rn(d[1], ch.y)));
                rm1 = fmaxf(rm1, fmaxf(__fsub_rn(d[2], ch.x),
                                       __fsub_rn(d[3], ch.y)));
            }
            rm0 = fmaxf(rm0, __shfl_xor_sync(0xffffffffu, rm0, 1));
            rm0 = fmaxf(rm0, __shfl_xor_sync(0xffffffffu, rm0, 2));
            rm1 = fmaxf(rm1, __shfl_xor_sync(0xffffffffu, rm1, 1));
            rm1 = fmaxf(rm1, __shfl_xor_sync(0xffffffffu, rm1, 2));
            const float cm = cmaxS[lvl];
            const float thr0 = rm0 -
                (MARG_REL * (r2sS[rowbase + g] + cm) + MARG_ABS);
            const float thr1 = rm1 -
                (MARG_REL * (r2sS[rowbase + g + 8] + cm) + MARG_ABS);

            // ---- pass 2: identical MMAs; push candidates ----
#pragma unroll 2
            for (int nt = 0; nt < 32; nt++) {
                const uint4* bp = reinterpret_cast<const uint4*>(
                    BL + (nt*32 + lane)*8);
                uint4 bA = bp[0], bB = bp[1];
                float d[4] = {0.f, 0.f, 0.f, 0.f};
                MMA_BF16(d, afr[0], bA.x, bA.y);
                MMA_BF16(d, afr[1], bA.z, bA.w);
                MMA_BF16(d, afr[2], bB.x, bB.y);
                MMA_BF16(d, afr[3], bB.z, bB.w);
                const float2 ch = *reinterpret_cast<const float2*>(
                    chL + nt*8 + 2*t4);
                const int col = nt*8 + 2*t4;
                const float s0 = __fsub_rn(d[0], ch.x);
                const float s1 = __fsub_rn(d[1], ch.y);
                const float s2 = __fsub_rn(d[2], ch.x);
                const float s3 = __fsub_rn(d[3], ch.y);
                if (s0 >= thr0) {
                    int pos = atomicAdd(&cntS[rowbase + g], 1);
                    if (pos < CAP) listS[(rowbase + g)*CAP + pos] = col;
                }
                if (s1 >= thr0) {
                    int pos = atomicAdd(&cntS[rowbase + g], 1);
                    if (pos < CAP) listS[(rowbase + g)*CAP + pos] = col + 1;
                }
                if (s2 >= thr1) {
                    int pos = atomicAdd(&cntS[rowbase + g + 8], 1);
                    if (pos < CAP) listS[(rowbase + g + 8)*CAP + pos] = col;
                }
                if (s3 >= thr1) {
                    int pos = atomicAdd(&cntS[rowbase + g + 8], 1);
                    if (pos < CAP) listS[(rowbase + g + 8)*CAP + pos] = col + 1;
                }
            }
            __syncthreads();

            // ---- exact re-check (pair-split, order-free tie-break) ----
            {
                const int c = cntS[q];
                const float r2q = r2sS[q];
                const float* rrow = Rs + (size_t)q * RS_STRIDE;
                float bestE = __int_as_float(0x7F800000);
                int bi = 0;
                if (c <= CAP) {
#pragma unroll 1
                    for (int i = h; i < c; i += 2) {
                        const int k = listS[q*CAP + i];
                        const float4* crow = reinterpret_cast<const float4*>(
                            cb + ((size_t)lvl * KCODES + k) * DIM);
                        float dot = 0.f;
#pragma unroll
                        for (int i2 = 0; i2 < 16; i2++) {
                            float4 cv = __ldg(crow + i2);
                            dot = fmaf(rrow[4*i2+0], cv.x, dot);
                            dot = fmaf(rrow[4*i2+1], cv.y, dot);
                            dot = fmaf(rrow[4*i2+2], cv.z, dot);
                            dot = fmaf(rrow[4*i2+3], cv.w, dot);
                        }
                        float de = __fadd_rn(
                            __fsub_rn(r2q, __fmul_rn(2.0f, dot)),
                            c2S[lvl*KCODES + k]);
                        if (de < bestE || (de == bestE && k < bi)) {
                            bestE = de; bi = k;
                        }
                    }
                } else {   // overflow: full exact scan (provably correct)
#pragma unroll 1
                    for (int k = h; k < KCODES; k += 2) {
                        const float4* crow = reinterpret_cast<const float4*>(
                            cb + ((size_t)lvl * KCODES + k) * DIM);
                        float dot = 0.f;
#pragma unroll
                        for (int i2 = 0; i2 < 16; i2++) {
                            float4 cv = __ldg(crow + i2);
                            dot = fmaf(rrow[4*i2+0], cv.x, dot);
                            dot = fmaf(rrow[4*i2+1], cv.y, dot);
                            dot = fmaf(rrow[4*i2+2], cv.z, dot);
                            dot = fmaf(rrow[4*i2+3], cv.w, dot);
                        }
                        float de = __fadd_rn(
                            __fsub_rn(r2q, __fmul_rn(2.0f, dot)),
                            c2S[lvl*KCODES + k]);
                        if (de < bestE || (de == bestE && k < bi)) {
                            bestE = de; bi = k;
                        }
                    }
                }
                const float od = __shfl_xor_sync(0xffffffffu, bestE, 1);
                const int ok = __shfl_xor_sync(0xffffffffu, bi, 1);
                if (od < bestE || (od == bestE && ok < bi)) {
                    bestE = od; bi = ok;
                }
                ids_[lvl] = bi;

                // exact residual update (pair-split halves)
                const float4* cw = reinterpret_cast<const float4*>(
                    cb + ((size_t)lvl * KCODES + bi) * DIM);
                float* rw = Rs + (size_t)q * RS_STRIDE;
#pragma unroll
                for (int i = h*8; i < h*8+8; i++) {
                    float4 cv = __ldg(cw + i);
                    rw[4*i+0] = __fsub_rn(rw[4*i+0], cv.x);
                    rw[4*i+1] = __fsub_rn(rw[4*i+1], cv.y);
                    rw[4*i+2] = __fsub_rn(rw[4*i+2], cv.z);
                    rw[4*i+3] = __fsub_rn(rw[4*i+3], cv.w);
                }
                __syncwarp();
                if (h == 0) {
                    float r2n = 0.f;
#pragma unroll
                    for (int j = 0; j < DIM; j++)
                        r2n = __fadd_rn(r2n, __fmul_rn(rw[j], rw[j]));
                    r2sS[q] = r2n;
                } else {
                    cntS[q] = 0;   // reset for next level/batch
                }
            }
        }

        // ---- epilogue (pair-split; validated vs reference) ----
        if (p_raw < B) {
            const float4* cp0 = reinterpret_cast<const float4*>(
                cb + ((size_t)0 * KCODES + ids_[0]) * DIM);
            const float4* cp1 = reinterpret_cast<const float4*>(
                cb + ((size_t)1 * KCODES + ids_[1]) * DIM);
            const float4* cp2 = reinterpret_cast<const float4*>(
                cb + ((size_t)2 * KCODES + ids_[2]) * DIM);
            const float4* cp3 = reinterpret_cast<const float4*>(
                cb + ((size_t)3 * KCODES + ids_[3]) * DIM);
            const float4* zp = reinterpret_cast<const float4*>(z + p * DIM);
            float4* qst = reinterpret_cast<float4*>(out + (size_t)p * DIM);
            float4* qq  = reinterpret_cast<float4*>(
                out + (size_t)B * (DIM + 4) + (size_t)p * DIM);
#pragma unroll
            for (int i = h*8; i < h*8+8; i++) {
                float4 v0 = __ldg(cp0 + i), v1 = __ldg(cp1 + i);
                float4 v2 = __ldg(cp2 + i), v3 = __ldg(cp3 + i);
                float4 qv;
                qv.x = __fadd_rn(__fadd_rn(__fadd_rn(v0.x, v1.x), v2.x), v3.x);
                qv.y = __fadd_rn(__fadd_rn(__fadd_rn(v0.y, v1.y), v2.y), v3.y);
                qv.z = __fadd_rn(__fadd_rn(__fadd_rn(v0.z, v1.z), v2.z), v3.z);
                qv.w = __fadd_rn(__fadd_rn(__fadd_rn(v0.w, v1.w), v2.w), v3.w);
                float4 zv = zp[i];
                float4 sv;
                sv.x = __fadd_rn(zv.x, __fsub_rn(qv.x, zv.x));
                sv.y = __fadd_rn(zv.y, __fsub_rn(qv.y, zv.y));
                sv.z = __fadd_rn(zv.z, __fsub_rn(qv.z, zv.z));
                sv.w = __fadd_rn(zv.w, __fsub_rn(qv.w, zv.w));
                qst[i] = sv;
                qq[i] = qv;
            }
            if (h == 0) {
                float4 iv;
                iv.x = (float)ids_[0]; iv.y = (float)ids_[1];
                iv.z = (float)ids_[2]; iv.w = (float)ids_[3];
                reinterpret_cast<float4*>(out + (size_t)B * DIM)[p] = iv;
            }
        }
    }
}

extern "C" void kernel_launch(void* const* d_in, const int* in_sizes, int n_in,
                              void* d_out, int out_size) {
    const float* z = (const float*)d_in[0];
    const float* cb = (const float*)d_in[1];
    float* out = (float*)d_out;
    int B = in_sizes[0] / DIM;
    int nbatch = (B + PTS - 1) / PTS;

    int dev = 0, nsm = 0;
    cudaGetDevice(&dev);
    cudaDeviceGetAttribute(&nsm, cudaDevAttrMultiProcessorCount, dev);
    if (nsm <= 0) nsm = 148;
    int grid = nsm < nbatch ? nsm : nbatch;

    cudaFuncSetAttribute(rq_kernel, cudaFuncAttributeMaxDynamicSharedMemorySize,
                         SMEM_TOTAL);
    rq_kernel<<<grid, TPB, SMEM_TOTAL>>>(z, cb, out, B, nbatch);
}